// round 2
// baseline (speedup 1.0000x reference)
#include <cuda_runtime.h>
#include <math.h>

// Problem constants (fixed by the reference)
constexpr int NNB  = 32;    // neighbors
constexpr int F0   = 16;
constexpr int F1   = 32;
constexpr int NENV = 8;
constexpr int DD   = 256;   // feature dim
constexpr int MAXROWS = 128 * 64;  // B*E

__device__ float g_mid[MAXROWS * DD];  // intermediate res (pre out-matmul)

// ---------------------------------------------------------------------------
// Kernel A: one CTA per (b,e) row. 256 threads.
// Stage 1: 8 threads per neighbor compute beta[32] and rescaled feats -> smem.
// Stage 2: thread d accumulates sum_n silu(feat) * (beta[n] . gamma[:,d]).
// ---------------------------------------------------------------------------
__global__ __launch_bounds__(256) void moon_phase1(
    const float* __restrict__ r,            // [BE,3]
    const float* __restrict__ r_nb,         // [BE,32,3]
    const float* __restrict__ ee_scales,    // [8]
    const float* __restrict__ ee_kernel,    // [4,16]
    const float* __restrict__ ee_bias,      // [16]
    const float* __restrict__ beta_kernel,  // [24,32]
    const float* __restrict__ beta_bias,    // [32]
    const float* __restrict__ gamma_kernel, // [32,256]
    const float* __restrict__ dense1_kernel,// [4,256]
    const float* __restrict__ dense1_bias)  // [256]
{
    __shared__ float s_beta[NNB][F1];
    __shared__ float s_inp[NNB][4];

    const int row = blockIdx.x;
    const int t   = threadIdx.x;

    // ---------------- stage 1 ----------------
    {
        const int n = t >> 3;   // neighbor 0..31
        const int j = t & 7;    // 8 threads per neighbor

        const float rx = r[row * 3 + 0];
        const float ry = r[row * 3 + 1];
        const float rz = r[row * 3 + 2];
        const float* nb = r_nb + ((long)row * NNB + n) * 3;
        const float dx = nb[0] - rx;
        const float dy = nb[1] - ry;
        const float dz = nb[2] - rz;
        const float dist = sqrtf(dx * dx + dy * dy + dz * dz);

        const float feats[4] = {dist, dx, dy, dz};

        float h[F0];
        #pragma unroll
        for (int k = 0; k < F0; k++) {
            float a = ee_bias[k];
            #pragma unroll
            for (int c = 0; c < 4; c++) a += feats[c] * ee_kernel[c * F0 + k];
            h[k] = tanhf(a);
        }

        float env[NENV];
        #pragma unroll
        for (int e = 0; e < NENV; e++) {
            float u = dist / ee_scales[e];
            env[e] = expf(-u * u);
        }

        const float x = dist * (1.0f / 5.0f);
        const float fcut = (x < 1.0f)
            ? 0.5f * (cosf(3.14159265358979323846f * x) + 1.0f)
            : 0.0f;

        #pragma unroll
        for (int fi = 0; fi < 4; fi++) {
            const int f = j * 4 + fi;
            float a = beta_bias[f];
            #pragma unroll
            for (int k = 0; k < F0; k++) a += h[k] * beta_kernel[k * F1 + f];
            #pragma unroll
            for (int e = 0; e < NENV; e++) a += env[e] * beta_kernel[(F0 + e) * F1 + f];
            s_beta[n][f] = a * fcut;
        }

        if (j == 0) {
            const float lp = log1pf(dist);
            const float sc = lp / dist;
            s_inp[n][0] = lp;       // dist column -> log1p(dist)
            s_inp[n][1] = dx * sc;
            s_inp[n][2] = dy * sc;
            s_inp[n][3] = dz * sc;
        }
    }
    __syncthreads();

    // ---------------- stage 2 ----------------
    {
        const int d = t;  // output feature dim

        float gcol[F1];
        #pragma unroll
        for (int f = 0; f < F1; f++) gcol[f] = gamma_kernel[f * DD + d];

        const float w0 = dense1_kernel[0 * DD + d];
        const float w1 = dense1_kernel[1 * DD + d];
        const float w2 = dense1_kernel[2 * DD + d];
        const float w3 = dense1_kernel[3 * DD + d];
        const float b1 = dense1_bias[d];

        float acc = 0.0f;
        #pragma unroll 4
        for (int n = 0; n < NNB; n++) {
            float g = 0.0f;
            #pragma unroll
            for (int f = 0; f < F1; f++) g += s_beta[n][f] * gcol[f];
            float pre = b1 + s_inp[n][0] * w0 + s_inp[n][1] * w1
                           + s_inp[n][2] * w2 + s_inp[n][3] * w3;
            float sg  = 1.0f / (1.0f + expf(-pre));
            acc += (pre * sg) * g;
        }
        g_mid[(long)row * DD + d] = acc;
    }
}

// ---------------------------------------------------------------------------
// Kernel B: Y = silu(g_mid @ W + bias).  X:[rows,256] W:[256,256].
// BM=BN=64, BK=16, 256 threads, 4x4 register tile per thread.
// ---------------------------------------------------------------------------
__global__ __launch_bounds__(256) void moon_out_gemm(
    const float* __restrict__ W,     // [256,256]
    const float* __restrict__ bias,  // [256]
    float* __restrict__ Y)           // [rows,256]
{
    constexpr int BM = 64, BN = 64, BK = 16;
    __shared__ float As[BK][BM + 1];
    __shared__ float Bs[BK][BN];

    const int tx = threadIdx.x & 15;
    const int ty = threadIdx.x >> 4;
    const int rowBase = blockIdx.y * BM;
    const int colBase = blockIdx.x * BN;

    float acc[4][4];
    #pragma unroll
    for (int i = 0; i < 4; i++)
        #pragma unroll
        for (int j = 0; j < 4; j++) acc[i][j] = 0.0f;

    const int t  = threadIdx.x;
    const int am = t >> 2;        // 0..63  (row within A tile)
    const int ak = (t & 3) * 4;   // 0,4,8,12
    const int bk = t >> 4;        // 0..15  (row within B tile)
    const int bn = (t & 15) * 4;  // 0..60

    for (int k0 = 0; k0 < DD; k0 += BK) {
        float4 av = *(const float4*)(g_mid + (long)(rowBase + am) * DD + k0 + ak);
        As[ak + 0][am] = av.x;
        As[ak + 1][am] = av.y;
        As[ak + 2][am] = av.z;
        As[ak + 3][am] = av.w;
        float4 bv = *(const float4*)(W + (long)(k0 + bk) * DD + colBase + bn);
        *(float4*)&Bs[bk][bn] = bv;
        __syncthreads();

        #pragma unroll
        for (int kk = 0; kk < BK; kk++) {
            float a0 = As[kk][ty * 4 + 0];
            float a1 = As[kk][ty * 4 + 1];
            float a2 = As[kk][ty * 4 + 2];
            float a3 = As[kk][ty * 4 + 3];
            float b0 = Bs[kk][tx * 4 + 0];
            float b1 = Bs[kk][tx * 4 + 1];
            float b2 = Bs[kk][tx * 4 + 2];
            float b3 = Bs[kk][tx * 4 + 3];
            acc[0][0] += a0 * b0; acc[0][1] += a0 * b1; acc[0][2] += a0 * b2; acc[0][3] += a0 * b3;
            acc[1][0] += a1 * b0; acc[1][1] += a1 * b1; acc[1][2] += a1 * b2; acc[1][3] += a1 * b3;
            acc[2][0] += a2 * b0; acc[2][1] += a2 * b1; acc[2][2] += a2 * b2; acc[2][3] += a2 * b3;
            acc[3][0] += a3 * b0; acc[3][1] += a3 * b1; acc[3][2] += a3 * b2; acc[3][3] += a3 * b3;
        }
        __syncthreads();
    }

    #pragma unroll
    for (int i = 0; i < 4; i++) {
        const int row = rowBase + ty * 4 + i;
        #pragma unroll
        for (int j = 0; j < 4; j++) {
            const int col = colBase + tx * 4 + j;
            float v  = acc[i][j] + bias[col];
            float sg = 1.0f / (1.0f + expf(-v));
            Y[(long)row * DD + col] = v * sg;
        }
    }
}

// ---------------------------------------------------------------------------
extern "C" void kernel_launch(void* const* d_in, const int* in_sizes, int n_in,
                              void* d_out, int out_size)
{
    const float* r             = (const float*)d_in[0];
    const float* r_nb          = (const float*)d_in[1];
    const float* ee_scales     = (const float*)d_in[2];
    const float* ee_kernel     = (const float*)d_in[3];
    const float* ee_bias       = (const float*)d_in[4];
    const float* beta_kernel   = (const float*)d_in[5];
    const float* beta_bias     = (const float*)d_in[6];
    const float* gamma_kernel  = (const float*)d_in[7];
    const float* dense1_kernel = (const float*)d_in[8];
    const float* dense1_bias   = (const float*)d_in[9];
    const float* out_kernel    = (const float*)d_in[10];
    const float* out_bias      = (const float*)d_in[11];

    const int rows = in_sizes[0] / 3;  // B*E = 8192

    moon_phase1<<<rows, 256>>>(r, r_nb, ee_scales, ee_kernel, ee_bias,
                               beta_kernel, beta_bias, gamma_kernel,
                               dense1_kernel, dense1_bias);

    dim3 gridB(DD / 64, rows / 64);
    moon_out_gemm<<<gridB, 256>>>(out_kernel, out_bias, (float*)d_out);
}

// round 3
// speedup vs baseline: 2.7342x; 2.7342x over previous
#include <cuda_runtime.h>
#include <math.h>

constexpr int NNB  = 32;
constexpr int F0   = 16;
constexpr int F1   = 32;
constexpr int NENV = 8;
constexpr int CC   = 25;    // 16 h + 8 env + 1 bias column
constexpr int DD   = 256;
constexpr int MAXROWS = 128 * 64;

__device__ float g_mid[MAXROWS * DD];
__device__ float g_WG[CC * DD];     // [25,256] folded beta_kernel(+bias) @ gamma

// ---------------------------------------------------------------------------
// Setup: WG[c,d] = sum_k Wb[c,k] * G[k,d]  (c<24), row 24 = beta_bias @ G.
// grid=25, block=256.  Cheap (~2us), runs before phase1 on the same stream.
// ---------------------------------------------------------------------------
__global__ void moon_wg(const float* __restrict__ Wb,   // [24,32]
                        const float* __restrict__ bb,   // [32]
                        const float* __restrict__ G)    // [32,256]
{
    const int c = blockIdx.x;
    const int d = threadIdx.x;
    float a = 0.0f;
    if (c < F0 + NENV) {
        #pragma unroll
        for (int k = 0; k < F1; k++) a += Wb[c * F1 + k] * G[k * DD + d];
    } else {
        #pragma unroll
        for (int k = 0; k < F1; k++) a += bb[k] * G[k * DD + d];
    }
    g_WG[c * DD + d] = a;
}

// ---------------------------------------------------------------------------
// Phase 1: one CTA = 2 (b,e) rows, 256 threads (128 per row).
// Stage 1: 4 threads/neighbor compute z'[n,0..24] (fcut folded in) + inp[n,0..3].
// Stage 2: thread owns d and d+128; 50 register accumulators V[c][2];
//          per neighbor: 8 LDS feed ~58 FFMA (register-blocked rank update).
// Epilogue: res_d = sum_c WG[c,d] * V[c,d]  -> g_mid.
// ---------------------------------------------------------------------------
__global__ __launch_bounds__(256) void moon_phase1(
    const float* __restrict__ r,             // [BE,3]
    const float* __restrict__ r_nb,          // [BE,32,3]
    const float* __restrict__ ee_scales,     // [8]
    const float* __restrict__ ee_kernel,     // [4,16]
    const float* __restrict__ ee_bias,       // [16]
    const float* __restrict__ dense1_kernel, // [4,256]
    const float* __restrict__ dense1_bias)   // [256]
{
    __shared__ __align__(16) float s_z[2][NNB][28];   // c stride 28 (16B aligned)
    __shared__ __align__(16) float s_inp[2][NNB][4];

    const int t    = threadIdx.x;
    const int half = t >> 7;
    const int u    = t & 127;
    const long row = (long)blockIdx.x * 2 + half;

    // ---------------- stage 1 ----------------
    {
        const int n = u >> 2;   // neighbor
        const int j = u & 3;    // 4 threads per neighbor

        const float rx = r[row * 3 + 0];
        const float ry = r[row * 3 + 1];
        const float rz = r[row * 3 + 2];
        const float* nb = r_nb + (row * NNB + n) * 3;
        const float dx = nb[0] - rx;
        const float dy = nb[1] - ry;
        const float dz = nb[2] - rz;
        const float dist = sqrtf(dx * dx + dy * dy + dz * dz);

        const float x = dist * 0.2f;
        const float fcut = (x < 1.0f)
            ? 0.5f * (cosf(3.14159265358979323846f * x) + 1.0f)
            : 0.0f;

        // 4 tanh features
        #pragma unroll
        for (int kk = 0; kk < 4; kk++) {
            const int k = j * 4 + kk;
            float a = ee_bias[k]
                    + dist * ee_kernel[0 * F0 + k]
                    + dx   * ee_kernel[1 * F0 + k]
                    + dy   * ee_kernel[2 * F0 + k]
                    + dz   * ee_kernel[3 * F0 + k];
            s_z[half][n][k] = tanhf(a) * fcut;
        }
        // 2 envelope features
        #pragma unroll
        for (int m = 0; m < 2; m++) {
            const int e = j * 2 + m;
            const float q = __fdividef(dist, ee_scales[e]);
            s_z[half][n][F0 + e] = __expf(-q * q) * fcut;
        }
        if (j == 0) {
            s_z[half][n][24] = fcut;  // constant column (carries beta_bias term)
            const float lp = log1pf(dist);
            const float sc = __fdividef(lp, dist);
            s_inp[half][n][0] = lp;
            s_inp[half][n][1] = dx * sc;
            s_inp[half][n][2] = dy * sc;
            s_inp[half][n][3] = dz * sc;
        }
    }
    __syncthreads();

    // ---------------- stage 2 ----------------
    {
        const int d0 = u;
        const int d1 = u + 128;

        const float w0a = dense1_kernel[0 * DD + d0], w0b = dense1_kernel[0 * DD + d1];
        const float w1a = dense1_kernel[1 * DD + d0], w1b = dense1_kernel[1 * DD + d1];
        const float w2a = dense1_kernel[2 * DD + d0], w2b = dense1_kernel[2 * DD + d1];
        const float w3a = dense1_kernel[3 * DD + d0], w3b = dense1_kernel[3 * DD + d1];
        const float b1a = dense1_bias[d0],            b1b = dense1_bias[d1];

        float V0[CC], V1[CC];
        #pragma unroll
        for (int c = 0; c < CC; c++) { V0[c] = 0.0f; V1[c] = 0.0f; }

        #pragma unroll 4
        for (int n = 0; n < NNB; n++) {
            const float4 ip = *(const float4*)s_inp[half][n];

            float pre0 = fmaf(ip.x, w0a, fmaf(ip.y, w1a, fmaf(ip.z, w2a, fmaf(ip.w, w3a, b1a))));
            float pre1 = fmaf(ip.x, w0b, fmaf(ip.y, w1b, fmaf(ip.z, w2b, fmaf(ip.w, w3b, b1b))));
            const float f0 = __fdividef(pre0, 1.0f + __expf(-pre0));  // silu
            const float f1 = __fdividef(pre1, 1.0f + __expf(-pre1));

            const float* zp = s_z[half][n];
            #pragma unroll
            for (int q = 0; q < 6; q++) {
                const float4 z = *(const float4*)(zp + q * 4);
                V0[q*4+0] = fmaf(z.x, f0, V0[q*4+0]);  V1[q*4+0] = fmaf(z.x, f1, V1[q*4+0]);
                V0[q*4+1] = fmaf(z.y, f0, V0[q*4+1]);  V1[q*4+1] = fmaf(z.y, f1, V1[q*4+1]);
                V0[q*4+2] = fmaf(z.z, f0, V0[q*4+2]);  V1[q*4+2] = fmaf(z.z, f1, V1[q*4+2]);
                V0[q*4+3] = fmaf(z.w, f0, V0[q*4+3]);  V1[q*4+3] = fmaf(z.w, f1, V1[q*4+3]);
            }
            const float z24 = zp[24];
            V0[24] = fmaf(z24, f0, V0[24]);
            V1[24] = fmaf(z24, f1, V1[24]);
        }

        float r0 = 0.0f, r1 = 0.0f;
        #pragma unroll
        for (int c = 0; c < CC; c++) {
            r0 = fmaf(g_WG[c * DD + d0], V0[c], r0);
            r1 = fmaf(g_WG[c * DD + d1], V1[c], r1);
        }
        g_mid[row * DD + d0] = r0;
        g_mid[row * DD + d1] = r1;
    }
}

// ---------------------------------------------------------------------------
// Kernel B: Y = silu(g_mid @ W + bias).  BM=128, BN=64, BK=16, 256 thr,
// 8x4 register tile per thread, float4 smem reads (3 LDS.128 per 32 FFMA).
// ---------------------------------------------------------------------------
__global__ __launch_bounds__(256) void moon_out_gemm(
    const float* __restrict__ W,     // [256,256]
    const float* __restrict__ bias,  // [256]
    float* __restrict__ Y)           // [rows,256]
{
    constexpr int BM = 128, BN = 64, BK = 16;
    __shared__ __align__(16) float As[BK][BM];
    __shared__ __align__(16) float Bs[BK][BN];

    const int t  = threadIdx.x;
    const int tx = t & 15;          // 4 cols each
    const int ty = t >> 4;          // 8 rows each
    const long rowBase = (long)blockIdx.y * BM;
    const int  colBase = blockIdx.x * BN;

    // A load mapping: 2 float4 per thread, scattered transposed into As
    const int ar  = t >> 1;         // 0..127
    const int akq = (t & 1) * 8;    // 0 or 8
    // B load mapping: 1 float4 per thread
    const int bk = t >> 4;          // 0..15
    const int bn = (t & 15) * 4;    // 0..60

    float acc[8][4];
    #pragma unroll
    for (int i = 0; i < 8; i++)
        #pragma unroll
        for (int j = 0; j < 4; j++) acc[i][j] = 0.0f;

    for (int k0 = 0; k0 < DD; k0 += BK) {
        const float4 av0 = *(const float4*)(g_mid + (rowBase + ar) * DD + k0 + akq);
        const float4 av1 = *(const float4*)(g_mid + (rowBase + ar) * DD + k0 + akq + 4);
        As[akq + 0][ar] = av0.x;  As[akq + 1][ar] = av0.y;
        As[akq + 2][ar] = av0.z;  As[akq + 3][ar] = av0.w;
        As[akq + 4][ar] = av1.x;  As[akq + 5][ar] = av1.y;
        As[akq + 6][ar] = av1.z;  As[akq + 7][ar] = av1.w;
        const float4 bv = *(const float4*)(W + (long)(k0 + bk) * DD + colBase + bn);
        *(float4*)&Bs[bk][bn] = bv;
        __syncthreads();

        #pragma unroll
        for (int kk = 0; kk < BK; kk++) {
            const float4 a0 = *(const float4*)&As[kk][ty * 8];
            const float4 a1 = *(const float4*)&As[kk][ty * 8 + 4];
            const float4 b  = *(const float4*)&Bs[kk][tx * 4];
            acc[0][0] = fmaf(a0.x, b.x, acc[0][0]); acc[0][1] = fmaf(a0.x, b.y, acc[0][1]);
            acc[0][2] = fmaf(a0.x, b.z, acc[0][2]); acc[0][3] = fmaf(a0.x, b.w, acc[0][3]);
            acc[1][0] = fmaf(a0.y, b.x, acc[1][0]); acc[1][1] = fmaf(a0.y, b.y, acc[1][1]);
            acc[1][2] = fmaf(a0.y, b.z, acc[1][2]); acc[1][3] = fmaf(a0.y, b.w, acc[1][3]);
            acc[2][0] = fmaf(a0.z, b.x, acc[2][0]); acc[2][1] = fmaf(a0.z, b.y, acc[2][1]);
            acc[2][2] = fmaf(a0.z, b.z, acc[2][2]); acc[2][3] = fmaf(a0.z, b.w, acc[2][3]);
            acc[3][0] = fmaf(a0.w, b.x, acc[3][0]); acc[3][1] = fmaf(a0.w, b.y, acc[3][1]);
            acc[3][2] = fmaf(a0.w, b.z, acc[3][2]); acc[3][3] = fmaf(a0.w, b.w, acc[3][3]);
            acc[4][0] = fmaf(a1.x, b.x, acc[4][0]); acc[4][1] = fmaf(a1.x, b.y, acc[4][1]);
            acc[4][2] = fmaf(a1.x, b.z, acc[4][2]); acc[4][3] = fmaf(a1.x, b.w, acc[4][3]);
            acc[5][0] = fmaf(a1.y, b.x, acc[5][0]); acc[5][1] = fmaf(a1.y, b.y, acc[5][1]);
            acc[5][2] = fmaf(a1.y, b.z, acc[5][2]); acc[5][3] = fmaf(a1.y, b.w, acc[5][3]);
            acc[6][0] = fmaf(a1.z, b.x, acc[6][0]); acc[6][1] = fmaf(a1.z, b.y, acc[6][1]);
            acc[6][2] = fmaf(a1.z, b.z, acc[6][2]); acc[6][3] = fmaf(a1.z, b.w, acc[6][3]);
            acc[7][0] = fmaf(a1.w, b.x, acc[7][0]); acc[7][1] = fmaf(a1.w, b.y, acc[7][1]);
            acc[7][2] = fmaf(a1.w, b.z, acc[7][2]); acc[7][3] = fmaf(a1.w, b.w, acc[7][3]);
        }
        __syncthreads();
    }

    const float4 bsv = *(const float4*)(bias + colBase + tx * 4);
    const float bb[4] = {bsv.x, bsv.y, bsv.z, bsv.w};
    #pragma unroll
    for (int i = 0; i < 8; i++) {
        const long row = rowBase + ty * 8 + i;
        float4 o;
        float v;
        v = acc[i][0] + bb[0]; o.x = __fdividef(v, 1.0f + __expf(-v));
        v = acc[i][1] + bb[1]; o.y = __fdividef(v, 1.0f + __expf(-v));
        v = acc[i][2] + bb[2]; o.z = __fdividef(v, 1.0f + __expf(-v));
        v = acc[i][3] + bb[3]; o.w = __fdividef(v, 1.0f + __expf(-v));
        *(float4*)(Y + row * DD + colBase + tx * 4) = o;
    }
}

// ---------------------------------------------------------------------------
extern "C" void kernel_launch(void* const* d_in, const int* in_sizes, int n_in,
                              void* d_out, int out_size)
{
    const float* r             = (const float*)d_in[0];
    const float* r_nb          = (const float*)d_in[1];
    const float* ee_scales     = (const float*)d_in[2];
    const float* ee_kernel     = (const float*)d_in[3];
    const float* ee_bias       = (const float*)d_in[4];
    const float* beta_kernel   = (const float*)d_in[5];
    const float* beta_bias     = (const float*)d_in[6];
    const float* gamma_kernel  = (const float*)d_in[7];
    const float* dense1_kernel = (const float*)d_in[8];
    const float* dense1_bias   = (const float*)d_in[9];
    const float* out_kernel    = (const float*)d_in[10];
    const float* out_bias      = (const float*)d_in[11];

    const int rows = in_sizes[0] / 3;  // 8192

    moon_wg<<<CC, 256>>>(beta_kernel, beta_bias, gamma_kernel);

    moon_phase1<<<rows / 2, 256>>>(r, r_nb, ee_scales, ee_kernel, ee_bias,
                                   dense1_kernel, dense1_bias);

    dim3 gridB(DD / 64, rows / 128);
    moon_out_gemm<<<gridB, 256>>>(out_kernel, out_bias, (float*)d_out);
}

// round 4
// speedup vs baseline: 2.9936x; 1.0949x over previous
#include <cuda_runtime.h>
#include <math.h>

constexpr int NNB  = 32;
constexpr int F0   = 16;
constexpr int F1   = 32;
constexpr int CCP  = 14;    // c-pairs: c=0..27 (25 real: 16 h + 8 env + bias; 3 zero pad)
constexpr int DD   = 256;
constexpr int MAXROWS = 128 * 64;

__device__ float g_mid[MAXROWS * DD];
__device__ __align__(16) float g_WGp[CCP * DD * 2];  // pair-interleaved folded (beta@gamma)

// ---------------- f32x2 packed helpers (sm_100+) ----------------
__device__ __forceinline__ unsigned long long pack2(float lo, float hi) {
    unsigned long long r;
    asm("mov.b64 %0, {%1, %2};" : "=l"(r) : "f"(lo), "f"(hi));
    return r;
}
__device__ __forceinline__ unsigned long long fma2(unsigned long long a,
                                                   unsigned long long b,
                                                   unsigned long long c) {
    unsigned long long d;
    asm("fma.rn.f32x2 %0, %1, %2, %3;" : "=l"(d) : "l"(a), "l"(b), "l"(c));
    return d;
}
__device__ __forceinline__ float2 unpack2(unsigned long long v) {
    float2 r;
    asm("mov.b64 {%0, %1}, %2;" : "=f"(r.x), "=f"(r.y) : "l"(v));
    return r;
}
__device__ __forceinline__ float tanh_approx(float x) {
    float y;
    asm("tanh.approx.f32 %0, %1;" : "=f"(y) : "f"(x));
    return y;
}

// ---------------------------------------------------------------------------
// Setup: pair-interleaved WG.  c<24: Wb row @ G.  c==24: beta_bias @ G.
// c in 25..27: zero pad.  g_WGp[(c>>1)*512 + d*2 + (c&1)].
// ---------------------------------------------------------------------------
__global__ void moon_wg(const float* __restrict__ Wb,   // [24,32]
                        const float* __restrict__ bb,   // [32]
                        const float* __restrict__ G)    // [32,256]
{
    const int c = blockIdx.x;   // 0..27
    const int d = threadIdx.x;
    float a = 0.0f;
    if (c < F0 + 8) {
        #pragma unroll
        for (int k = 0; k < F1; k++) a += Wb[c * F1 + k] * G[k * DD + d];
    } else if (c == 24) {
        #pragma unroll
        for (int k = 0; k < F1; k++) a += bb[k] * G[k * DD + d];
    }
    g_WGp[(c >> 1) * (DD * 2) + d * 2 + (c & 1)] = a;
}

// ---------------------------------------------------------------------------
// Phase 1: one CTA = 2 rows, 256 threads (128 per row).
// Stage 2 inner loop: 8 broadcast LDS.128 + 28 FFMA2 per neighbor.
// ---------------------------------------------------------------------------
__global__ __launch_bounds__(256, 2) void moon_phase1(
    const float* __restrict__ r,             // [BE,3]
    const float* __restrict__ r_nb,          // [BE,32,3]
    const float* __restrict__ ee_scales,     // [8]
    const float* __restrict__ ee_kernel,     // [4,16]
    const float* __restrict__ ee_bias,       // [16]
    const float* __restrict__ dense1_kernel, // [4,256]
    const float* __restrict__ dense1_bias)   // [256]
{
    __shared__ __align__(16) float s_z[2][NNB][28];   // row = 112B (16B aligned)
    __shared__ __align__(16) float s_inp[2][NNB][4];

    const int t    = threadIdx.x;
    const int half = t >> 7;
    const int u    = t & 127;
    const long row = (long)blockIdx.x * 2 + half;

    // ---------------- stage 1 ----------------
    {
        const int n = u >> 2;   // neighbor
        const int j = u & 3;    // 4 threads per neighbor

        const float rx = r[row * 3 + 0];
        const float ry = r[row * 3 + 1];
        const float rz = r[row * 3 + 2];
        const float* nb = r_nb + (row * NNB + n) * 3;
        const float dx = nb[0] - rx;
        const float dy = nb[1] - ry;
        const float dz = nb[2] - rz;
        const float dist = sqrtf(dx * dx + dy * dy + dz * dz);

        const float x = dist * 0.2f;
        const float fcut = (x < 1.0f)
            ? 0.5f * (__cosf(3.14159265358979323846f * x) + 1.0f)
            : 0.0f;

        #pragma unroll
        for (int kk = 0; kk < 4; kk++) {
            const int k = j * 4 + kk;
            float a = ee_bias[k]
                    + dist * ee_kernel[0 * F0 + k]
                    + dx   * ee_kernel[1 * F0 + k]
                    + dy   * ee_kernel[2 * F0 + k]
                    + dz   * ee_kernel[3 * F0 + k];
            s_z[half][n][k] = tanh_approx(a) * fcut;
        }
        #pragma unroll
        for (int m = 0; m < 2; m++) {
            const int e = j * 2 + m;
            const float q = __fdividef(dist, ee_scales[e]);
            s_z[half][n][F0 + e] = __expf(-q * q) * fcut;
        }
        if (j == 0) {
            *(float4*)&s_z[half][n][24] = make_float4(fcut, 0.0f, 0.0f, 0.0f);
            const float lp = __logf(1.0f + dist);
            const float sc = __fdividef(lp, dist);
            s_inp[half][n][0] = lp;
            s_inp[half][n][1] = dx * sc;
            s_inp[half][n][2] = dy * sc;
            s_inp[half][n][3] = dz * sc;
        }
    }
    __syncthreads();

    // ---------------- stage 2 ----------------
    {
        const int d0 = u;
        const int d1 = u + 128;

        const float w0a = dense1_kernel[0 * DD + d0], w0b = dense1_kernel[0 * DD + d1];
        const float w1a = dense1_kernel[1 * DD + d0], w1b = dense1_kernel[1 * DD + d1];
        const float w2a = dense1_kernel[2 * DD + d0], w2b = dense1_kernel[2 * DD + d1];
        const float w3a = dense1_kernel[3 * DD + d0], w3b = dense1_kernel[3 * DD + d1];
        const float b1a = dense1_bias[d0],            b1b = dense1_bias[d1];

        unsigned long long Vp0[CCP], Vp1[CCP];
        #pragma unroll
        for (int q = 0; q < CCP; q++) { Vp0[q] = 0ull; Vp1[q] = 0ull; }

        #pragma unroll 4
        for (int n = 0; n < NNB; n++) {
            const float4 ip = *(const float4*)s_inp[half][n];

            float pre0 = fmaf(ip.x, w0a, fmaf(ip.y, w1a, fmaf(ip.z, w2a, fmaf(ip.w, w3a, b1a))));
            float pre1 = fmaf(ip.x, w0b, fmaf(ip.y, w1b, fmaf(ip.z, w2b, fmaf(ip.w, w3b, b1b))));
            const float f0 = __fdividef(pre0, 1.0f + __expf(-pre0));
            const float f1 = __fdividef(pre1, 1.0f + __expf(-pre1));
            const unsigned long long ffa = pack2(f0, f0);
            const unsigned long long ffb = pack2(f1, f1);

            const ulonglong2* zp = (const ulonglong2*)&s_z[half][n][0];
            #pragma unroll
            for (int q = 0; q < 7; q++) {                 // broadcast LDS.128
                const ulonglong2 z2 = zp[q];              // c = 4q .. 4q+3
                Vp0[2*q+0] = fma2(z2.x, ffa, Vp0[2*q+0]);
                Vp0[2*q+1] = fma2(z2.y, ffa, Vp0[2*q+1]);
                Vp1[2*q+0] = fma2(z2.x, ffb, Vp1[2*q+0]);
                Vp1[2*q+1] = fma2(z2.y, ffb, Vp1[2*q+1]);
            }
        }

        // epilogue: res_d = sum_c WG[c,d] * V[c,d]  via pair-interleaved WG
        const unsigned long long* wgp = (const unsigned long long*)g_WGp;
        unsigned long long a0 = 0ull, a1 = 0ull;
        #pragma unroll
        for (int q = 0; q < CCP; q++) {
            a0 = fma2(wgp[q * DD + d0], Vp0[q], a0);
            a1 = fma2(wgp[q * DD + d1], Vp1[q], a1);
        }
        const float2 ua = unpack2(a0);
        const float2 ub = unpack2(a1);
        g_mid[row * DD + d0] = ua.x + ua.y;
        g_mid[row * DD + d1] = ub.x + ub.y;
    }
}

// ---------------------------------------------------------------------------
// Kernel B: Y = silu(g_mid @ W + bias).  BM=128, BN=64, BK=16, 256 thr.
// 8x4 thread tile as 4 row-pairs x 4 cols in f32x2: 16 FFMA2 + 4 packs / kk.
// ---------------------------------------------------------------------------
__global__ __launch_bounds__(256) void moon_out_gemm(
    const float* __restrict__ W,     // [256,256]
    const float* __restrict__ bias,  // [256]
    float* __restrict__ Y)           // [rows,256]
{
    constexpr int BM = 128, BN = 64, BK = 16;
    __shared__ __align__(16) float As[BK][BM];
    __shared__ __align__(16) float Bs[BK][BN];

    const int t  = threadIdx.x;
    const int tx = t & 15;          // 4 cols
    const int ty = t >> 4;          // 8 rows (4 pairs)
    const long rowBase = (long)blockIdx.y * BM;
    const int  colBase = blockIdx.x * BN;

    const int ar  = t >> 1;
    const int akq = (t & 1) * 8;
    const int bk = t >> 4;
    const int bn = (t & 15) * 4;

    unsigned long long accp[4][4];
    #pragma unroll
    for (int i = 0; i < 4; i++)
        #pragma unroll
        for (int j = 0; j < 4; j++) accp[i][j] = 0ull;

    for (int k0 = 0; k0 < DD; k0 += BK) {
        const float4 av0 = *(const float4*)(g_mid + (rowBase + ar) * DD + k0 + akq);
        const float4 av1 = *(const float4*)(g_mid + (rowBase + ar) * DD + k0 + akq + 4);
        As[akq + 0][ar] = av0.x;  As[akq + 1][ar] = av0.y;
        As[akq + 2][ar] = av0.z;  As[akq + 3][ar] = av0.w;
        As[akq + 4][ar] = av1.x;  As[akq + 5][ar] = av1.y;
        As[akq + 6][ar] = av1.z;  As[akq + 7][ar] = av1.w;
        *(float4*)&Bs[bk][bn] = *(const float4*)(W + (long)(k0 + bk) * DD + colBase + bn);
        __syncthreads();

        #pragma unroll
        for (int kk = 0; kk < BK; kk++) {
            const ulonglong2 aA = *(const ulonglong2*)&As[kk][ty * 8];      // row pairs 0,1
            const ulonglong2 aB = *(const ulonglong2*)&As[kk][ty * 8 + 4];  // row pairs 2,3
            const float4 b = *(const float4*)&Bs[kk][tx * 4];
            const unsigned long long b0 = pack2(b.x, b.x);
            const unsigned long long b1 = pack2(b.y, b.y);
            const unsigned long long b2 = pack2(b.z, b.z);
            const unsigned long long b3 = pack2(b.w, b.w);
            accp[0][0] = fma2(aA.x, b0, accp[0][0]);
            accp[0][1] = fma2(aA.x, b1, accp[0][1]);
            accp[0][2] = fma2(aA.x, b2, accp[0][2]);
            accp[0][3] = fma2(aA.x, b3, accp[0][3]);
            accp[1][0] = fma2(aA.y, b0, accp[1][0]);
            accp[1][1] = fma2(aA.y, b1, accp[1][1]);
            accp[1][2] = fma2(aA.y, b2, accp[1][2]);
            accp[1][3] = fma2(aA.y, b3, accp[1][3]);
            accp[2][0] = fma2(aB.x, b0, accp[2][0]);
            accp[2][1] = fma2(aB.x, b1, accp[2][1]);
            accp[2][2] = fma2(aB.x, b2, accp[2][2]);
            accp[2][3] = fma2(aB.x, b3, accp[2][3]);
            accp[3][0] = fma2(aB.y, b0, accp[3][0]);
            accp[3][1] = fma2(aB.y, b1, accp[3][1]);
            accp[3][2] = fma2(aB.y, b2, accp[3][2]);
            accp[3][3] = fma2(aB.y, b3, accp[3][3]);
        }
        __syncthreads();
    }

    const float4 bsv = *(const float4*)(bias + colBase + tx * 4);
    const float bb4[4] = {bsv.x, bsv.y, bsv.z, bsv.w};
    #pragma unroll
    for (int ip = 0; ip < 4; ip++) {
        float2 v[4];
        #pragma unroll
        for (int j = 0; j < 4; j++) v[j] = unpack2(accp[ip][j]);
        const long row0 = rowBase + ty * 8 + ip * 2;
        float4 o0, o1;
        float w;
        w = v[0].x + bb4[0]; o0.x = __fdividef(w, 1.0f + __expf(-w));
        w = v[1].x + bb4[1]; o0.y = __fdividef(w, 1.0f + __expf(-w));
        w = v[2].x + bb4[2]; o0.z = __fdividef(w, 1.0f + __expf(-w));
        w = v[3].x + bb4[3]; o0.w = __fdividef(w, 1.0f + __expf(-w));
        w = v[0].y + bb4[0]; o1.x = __fdividef(w, 1.0f + __expf(-w));
        w = v[1].y + bb4[1]; o1.y = __fdividef(w, 1.0f + __expf(-w));
        w = v[2].y + bb4[2]; o1.z = __fdividef(w, 1.0f + __expf(-w));
        w = v[3].y + bb4[3]; o1.w = __fdividef(w, 1.0f + __expf(-w));
        *(float4*)(Y + row0 * DD + colBase + tx * 4)       = o0;
        *(float4*)(Y + (row0 + 1) * DD + colBase + tx * 4) = o1;
    }
}

// ---------------------------------------------------------------------------
extern "C" void kernel_launch(void* const* d_in, const int* in_sizes, int n_in,
                              void* d_out, int out_size)
{
    const float* r             = (const float*)d_in[0];
    const float* r_nb          = (const float*)d_in[1];
    const float* ee_scales     = (const float*)d_in[2];
    const float* ee_kernel     = (const float*)d_in[3];
    const float* ee_bias       = (const float*)d_in[4];
    const float* beta_kernel   = (const float*)d_in[5];
    const float* beta_bias     = (const float*)d_in[6];
    const float* gamma_kernel  = (const float*)d_in[7];
    const float* dense1_kernel = (const float*)d_in[8];
    const float* dense1_bias   = (const float*)d_in[9];
    const float* out_kernel    = (const float*)d_in[10];
    const float* out_bias      = (const float*)d_in[11];

    const int rows = in_sizes[0] / 3;  // 8192

    moon_wg<<<2 * CCP, 256>>>(beta_kernel, beta_bias, gamma_kernel);

    moon_phase1<<<rows / 2, 256>>>(r, r_nb, ee_scales, ee_kernel, ee_bias,
                                   dense1_kernel, dense1_bias);

    dim3 gridB(DD / 64, rows / 128);
    moon_out_gemm<<<gridB, 256>>>(out_kernel, out_bias, (float*)d_out);
}

// round 6
// speedup vs baseline: 2.9991x; 1.0018x over previous
#include <cuda_runtime.h>
#include <cuda_bf16.h>
#include <math.h>
#include <stdint.h>

constexpr int NNB  = 32;
constexpr int F0   = 16;
constexpr int CCP  = 14;    // c-pairs: c=0..27 (25 real, 3 pad)
constexpr int DD   = 256;
constexpr int NROWS = 128 * 64;   // 8192

// folded (beta_kernel+bias) @ gamma, pair-interleaved
__device__ __align__(16) float g_WGp[CCP * DD * 2];

// A (phase1 result) bf16 hi/lo, row-major [8192][256]
__device__ __align__(16) __nv_bfloat16 g_Ah[NROWS * DD];
__device__ __align__(16) __nv_bfloat16 g_Al[NROWS * DD];
// W^T bf16 hi/lo, row-major [n=256][k=256]
__device__ __align__(16) __nv_bfloat16 g_WTh[DD * DD];
__device__ __align__(16) __nv_bfloat16 g_WTl[DD * DD];

// ---------------- helpers ----------------
__device__ __forceinline__ unsigned long long pack2(float lo, float hi) {
    unsigned long long r;
    asm("mov.b64 %0, {%1, %2};" : "=l"(r) : "f"(lo), "f"(hi));
    return r;
}
__device__ __forceinline__ unsigned long long fma2(unsigned long long a,
                                                   unsigned long long b,
                                                   unsigned long long c) {
    unsigned long long d;
    asm("fma.rn.f32x2 %0, %1, %2, %3;" : "=l"(d) : "l"(a), "l"(b), "l"(c));
    return d;
}
__device__ __forceinline__ float2 unpack2(unsigned long long v) {
    float2 r;
    asm("mov.b64 {%0, %1}, %2;" : "=f"(r.x), "=f"(r.y) : "l"(v));
    return r;
}
__device__ __forceinline__ float tanh_approx(float x) {
    float y;
    asm("tanh.approx.f32 %0, %1;" : "=f"(y) : "f"(x));
    return y;
}

#define MMA16816(d, a, b0v, b1v) \
    asm volatile("mma.sync.aligned.m16n8k16.row.col.f32.bf16.bf16.f32 " \
        "{%0,%1,%2,%3}, {%4,%5,%6,%7}, {%8,%9}, {%0,%1,%2,%3};" \
        : "+f"((d)[0]), "+f"((d)[1]), "+f"((d)[2]), "+f"((d)[3]) \
        : "r"((a)[0]), "r"((a)[1]), "r"((a)[2]), "r"((a)[3]), "r"(b0v), "r"(b1v))

// ---------------------------------------------------------------------------
// Setup (one launch): blocks 0..255 -> W^T bf16 hi/lo split; 256..283 -> WG fold.
// ---------------------------------------------------------------------------
__global__ void moon_setup(const float* __restrict__ Wb,   // [24,32]
                           const float* __restrict__ bb,   // [32]
                           const float* __restrict__ G,    // [32,256]
                           const float* __restrict__ W)    // [256,256]
{
    const int b = blockIdx.x;
    if (b < 256) {
        const int n = b;
        const int k = threadIdx.x;
        const float w = W[k * DD + n];
        const __nv_bfloat16 h = __float2bfloat16(w);
        g_WTh[n * DD + k] = h;
        g_WTl[n * DD + k] = __float2bfloat16(w - __bfloat162float(h));
    } else {
        const int c = b - 256;   // 0..27
        const int d = threadIdx.x;
        float a = 0.0f;
        if (c < F0 + 8) {
            #pragma unroll
            for (int k = 0; k < 32; k++) a += Wb[c * 32 + k] * G[k * DD + d];
        } else if (c == 24) {
            #pragma unroll
            for (int k = 0; k < 32; k++) a += bb[k] * G[k * DD + d];
        }
        g_WGp[(c >> 1) * (DD * 2) + d * 2 + (c & 1)] = a;
    }
}

// ---------------------------------------------------------------------------
// Phase 1 (round-4 math; epilogue emits bf16 hi/lo row-major)
// ---------------------------------------------------------------------------
__global__ __launch_bounds__(256, 2) void moon_phase1(
    const float* __restrict__ r,
    const float* __restrict__ r_nb,
    const float* __restrict__ ee_scales,
    const float* __restrict__ ee_kernel,
    const float* __restrict__ ee_bias,
    const float* __restrict__ dense1_kernel,
    const float* __restrict__ dense1_bias)
{
    __shared__ __align__(16) float s_z[2][NNB][28];
    __shared__ __align__(16) float s_inp[2][NNB][4];

    const int t    = threadIdx.x;
    const int half = t >> 7;
    const int u    = t & 127;
    const long row = (long)blockIdx.x * 2 + half;

    {
        const int n = u >> 2;
        const int j = u & 3;

        const float rx = r[row * 3 + 0];
        const float ry = r[row * 3 + 1];
        const float rz = r[row * 3 + 2];
        const float* nb = r_nb + (row * NNB + n) * 3;
        const float dx = nb[0] - rx;
        const float dy = nb[1] - ry;
        const float dz = nb[2] - rz;
        const float dist = sqrtf(dx * dx + dy * dy + dz * dz);

        const float x = dist * 0.2f;
        const float fcut = (x < 1.0f)
            ? 0.5f * (__cosf(3.14159265358979323846f * x) + 1.0f)
            : 0.0f;

        #pragma unroll
        for (int kk = 0; kk < 4; kk++) {
            const int k = j * 4 + kk;
            float a = ee_bias[k]
                    + dist * ee_kernel[0 * F0 + k]
                    + dx   * ee_kernel[1 * F0 + k]
                    + dy   * ee_kernel[2 * F0 + k]
                    + dz   * ee_kernel[3 * F0 + k];
            s_z[half][n][k] = tanh_approx(a) * fcut;
        }
        #pragma unroll
        for (int m = 0; m < 2; m++) {
            const int e = j * 2 + m;
            const float q = __fdividef(dist, ee_scales[e]);
            s_z[half][n][F0 + e] = __expf(-q * q) * fcut;
        }
        if (j == 0) {
            *(float4*)&s_z[half][n][24] = make_float4(fcut, 0.0f, 0.0f, 0.0f);
            const float lp = __logf(1.0f + dist);
            const float sc = __fdividef(lp, dist);
            s_inp[half][n][0] = lp;
            s_inp[half][n][1] = dx * sc;
            s_inp[half][n][2] = dy * sc;
            s_inp[half][n][3] = dz * sc;
        }
    }
    __syncthreads();

    {
        const int d0 = u;
        const int d1 = u + 128;

        const float w0a = dense1_kernel[0 * DD + d0], w0b = dense1_kernel[0 * DD + d1];
        const float w1a = dense1_kernel[1 * DD + d0], w1b = dense1_kernel[1 * DD + d1];
        const float w2a = dense1_kernel[2 * DD + d0], w2b = dense1_kernel[2 * DD + d1];
        const float w3a = dense1_kernel[3 * DD + d0], w3b = dense1_kernel[3 * DD + d1];
        const float b1a = dense1_bias[d0],            b1b = dense1_bias[d1];

        unsigned long long Vp0[CCP], Vp1[CCP];
        #pragma unroll
        for (int q = 0; q < CCP; q++) { Vp0[q] = 0ull; Vp1[q] = 0ull; }

        #pragma unroll 4
        for (int n = 0; n < NNB; n++) {
            const float4 ip = *(const float4*)s_inp[half][n];

            float pre0 = fmaf(ip.x, w0a, fmaf(ip.y, w1a, fmaf(ip.z, w2a, fmaf(ip.w, w3a, b1a))));
            float pre1 = fmaf(ip.x, w0b, fmaf(ip.y, w1b, fmaf(ip.z, w2b, fmaf(ip.w, w3b, b1b))));
            const float f0 = __fdividef(pre0, 1.0f + __expf(-pre0));
            const float f1 = __fdividef(pre1, 1.0f + __expf(-pre1));
            const unsigned long long ffa = pack2(f0, f0);
            const unsigned long long ffb = pack2(f1, f1);

            const ulonglong2* zp = (const ulonglong2*)&s_z[half][n][0];
            #pragma unroll
            for (int q = 0; q < 7; q++) {
                const ulonglong2 z2 = zp[q];
                Vp0[2*q+0] = fma2(z2.x, ffa, Vp0[2*q+0]);
                Vp0[2*q+1] = fma2(z2.y, ffa, Vp0[2*q+1]);
                Vp1[2*q+0] = fma2(z2.x, ffb, Vp1[2*q+0]);
                Vp1[2*q+1] = fma2(z2.y, ffb, Vp1[2*q+1]);
            }
        }

        const unsigned long long* wgp = (const unsigned long long*)g_WGp;
        unsigned long long a0 = 0ull, a1 = 0ull;
        #pragma unroll
        for (int q = 0; q < CCP; q++) {
            a0 = fma2(wgp[q * DD + d0], Vp0[q], a0);
            a1 = fma2(wgp[q * DD + d1], Vp1[q], a1);
        }
        const float2 ua = unpack2(a0);
        const float2 ub = unpack2(a1);
        const float res0 = ua.x + ua.y;
        const float res1 = ub.x + ub.y;

        const __nv_bfloat16 h0 = __float2bfloat16(res0);
        const __nv_bfloat16 h1 = __float2bfloat16(res1);
        g_Ah[row * DD + d0] = h0;
        g_Al[row * DD + d0] = __float2bfloat16(res0 - __bfloat162float(h0));
        g_Ah[row * DD + d1] = h1;
        g_Al[row * DD + d1] = __float2bfloat16(res1 - __bfloat162float(h1));
    }
}

// ---------------------------------------------------------------------------
// Kernel B (mma.sync bf16, 3-chain compensated):
// Y = silu(A @ W + bias).  CTA tile 128x128, 8 warps (4M x 2N), K chunks of 64.
// ---------------------------------------------------------------------------
constexpr int KS = 88;                 // smem k-stride in bf16 (176B rows, conflict-free)
constexpr int TILE_BYTES = 128 * KS * 2;

__global__ __launch_bounds__(256) void moon_gemm_mma(
    const float* __restrict__ bias, float* __restrict__ Y)
{
    extern __shared__ __align__(16) char smem[];
    __nv_bfloat16* sAh = (__nv_bfloat16*)(smem);
    __nv_bfloat16* sAl = (__nv_bfloat16*)(smem + TILE_BYTES);
    __nv_bfloat16* sBh = (__nv_bfloat16*)(smem + 2 * TILE_BYTES);
    __nv_bfloat16* sBl = (__nv_bfloat16*)(smem + 3 * TILE_BYTES);

    const int t    = threadIdx.x;
    const int lane = t & 31;
    const int wid  = t >> 5;
    const int gid  = lane >> 2;    // group 0..7
    const int tig  = lane & 3;     // 0..3
    const int warp_m = wid & 3;    // M offset 32*warp_m
    const int warp_n = wid >> 2;   // N offset 64*warp_n
    const int ct   = blockIdx.x;   // 0..1
    const int rowT = blockIdx.y;   // 0..63

    float acc[2][8][4];
    #pragma unroll
    for (int mf = 0; mf < 2; mf++)
        #pragma unroll
        for (int j = 0; j < 8; j++)
            #pragma unroll
            for (int c = 0; c < 4; c++) acc[mf][j][c] = 0.0f;

    const size_t aBase = (size_t)(rowT * 128) * DD;
    const size_t bBase = (size_t)(ct * 128) * DD;

    for (int kc = 0; kc < 4; kc++) {
        // ---- stage 64-wide K chunk into smem ----
        #pragma unroll
        for (int i = 0; i < 4; i++) {
            const int lin = t + i * 256;       // 0..1023
            const int rr  = lin >> 3;          // 0..127
            const int kq  = (lin & 7) * 8;     // 0..56
            const size_t goff = (size_t)rr * DD + kc * 64 + kq;
            const int soff = rr * KS + kq;
            *(uint4*)&sAh[soff] = *(const uint4*)&g_Ah[aBase + goff];
            *(uint4*)&sAl[soff] = *(const uint4*)&g_Al[aBase + goff];
            *(uint4*)&sBh[soff] = *(const uint4*)&g_WTh[bBase + goff];
            *(uint4*)&sBl[soff] = *(const uint4*)&g_WTl[bBase + goff];
        }
        __syncthreads();

        #pragma unroll
        for (int k16 = 0; k16 < 4; k16++) {
            const int koff = k16 * 16;
            uint32_t ah[2][4], al[2][4];
            #pragma unroll
            for (int mf = 0; mf < 2; mf++) {
                const int mb = warp_m * 32 + mf * 16;
                const int r0 = (mb + gid) * KS + koff + 2 * tig;
                const int r1 = (mb + 8 + gid) * KS + koff + 2 * tig;
                ah[mf][0] = *(const uint32_t*)&sAh[r0];
                ah[mf][1] = *(const uint32_t*)&sAh[r1];
                ah[mf][2] = *(const uint32_t*)&sAh[r0 + 8];
                ah[mf][3] = *(const uint32_t*)&sAh[r1 + 8];
                al[mf][0] = *(const uint32_t*)&sAl[r0];
                al[mf][1] = *(const uint32_t*)&sAl[r1];
                al[mf][2] = *(const uint32_t*)&sAl[r0 + 8];
                al[mf][3] = *(const uint32_t*)&sAl[r1 + 8];
            }
            #pragma unroll
            for (int j = 0; j < 8; j++) {
                const int nb = (warp_n * 64 + j * 8 + gid) * KS + koff + 2 * tig;
                const uint32_t bh0 = *(const uint32_t*)&sBh[nb];
                const uint32_t bh1 = *(const uint32_t*)&sBh[nb + 8];
                const uint32_t bl0 = *(const uint32_t*)&sBl[nb];
                const uint32_t bl1 = *(const uint32_t*)&sBl[nb + 8];
                #pragma unroll
                for (int mf = 0; mf < 2; mf++) {
                    MMA16816(acc[mf][j], ah[mf], bh0, bh1);
                    MMA16816(acc[mf][j], ah[mf], bl0, bl1);
                    MMA16816(acc[mf][j], al[mf], bh0, bh1);
                }
            }
        }
        __syncthreads();
    }

    // ---- epilogue: bias + silu, direct float2 stores ----
    #pragma unroll
    for (int j = 0; j < 8; j++) {
        const int col = ct * 128 + warp_n * 64 + j * 8 + 2 * tig;
        const float2 bb = *(const float2*)&bias[col];
        #pragma unroll
        for (int mf = 0; mf < 2; mf++) {
            const long row0 = rowT * 128 + warp_m * 32 + mf * 16 + gid;
            float v0 = acc[mf][j][0] + bb.x;
            float v1 = acc[mf][j][1] + bb.y;
            float v2 = acc[mf][j][2] + bb.x;
            float v3 = acc[mf][j][3] + bb.y;
            float2 o0, o1;
            o0.x = __fdividef(v0, 1.0f + __expf(-v0));
            o0.y = __fdividef(v1, 1.0f + __expf(-v1));
            o1.x = __fdividef(v2, 1.0f + __expf(-v2));
            o1.y = __fdividef(v3, 1.0f + __expf(-v3));
            *(float2*)&Y[row0 * DD + col]       = o0;
            *(float2*)&Y[(row0 + 8) * DD + col] = o1;
        }
    }
}

// ---------------------------------------------------------------------------
extern "C" void kernel_launch(void* const* d_in, const int* in_sizes, int n_in,
                              void* d_out, int out_size)
{
    const float* r             = (const float*)d_in[0];
    const float* r_nb          = (const float*)d_in[1];
    const float* ee_scales     = (const float*)d_in[2];
    const float* ee_kernel     = (const float*)d_in[3];
    const float* ee_bias       = (const float*)d_in[4];
    const float* beta_kernel   = (const float*)d_in[5];
    const float* beta_bias     = (const float*)d_in[6];
    const float* gamma_kernel  = (const float*)d_in[7];
    const float* dense1_kernel = (const float*)d_in[8];
    const float* dense1_bias   = (const float*)d_in[9];
    const float* out_kernel    = (const float*)d_in[10];
    const float* out_bias      = (const float*)d_in[11];

    const int rows = in_sizes[0] / 3;  // 8192

    static bool attr_done = false;
    if (!attr_done) {
        cudaFuncSetAttribute(moon_gemm_mma,
                             cudaFuncAttributeMaxDynamicSharedMemorySize,
                             4 * TILE_BYTES);
        attr_done = true;
    }

    moon_setup<<<256 + 28, 256>>>(beta_kernel, beta_bias, gamma_kernel, out_kernel);

    moon_phase1<<<rows / 2, 256>>>(r, r_nb, ee_scales, ee_kernel, ee_bias,
                                   dense1_kernel, dense1_bias);

    dim3 gridB(2, rows / 128);
    moon_gemm_mma<<<gridB, 256, 4 * TILE_BYTES>>>(out_bias, (float*)d_out);
}

// round 9
// speedup vs baseline: 4.1863x; 1.3959x over previous
#include <cuda_runtime.h>
#include <cuda_bf16.h>
#include <math.h>
#include <stdint.h>

constexpr int NNB  = 32;
constexpr int F0   = 16;
constexpr int DD   = 256;
constexpr int NROWS = 8192;       // B*E
constexpr int ZS   = 40;          // smem z row stride in bf16 (80B -> conflict-free frags)

// A (phase1 result) bf16 hi/lo, row-major [8192][256]
__device__ __align__(16) __nv_bfloat16 g_Ah[NROWS * DD];
__device__ __align__(16) __nv_bfloat16 g_Al[NROWS * DD];
// out_kernel^T bf16 hi/lo, row-major [n=256][k=256]
__device__ __align__(16) __nv_bfloat16 g_WTh[DD * DD];
__device__ __align__(16) __nv_bfloat16 g_WTl[DD * DD];
// WG^T = (fold of beta_kernel/bias @ gamma)^T, bf16 hi/lo, [d=256][c=32] (c>=25 zero)
__device__ __align__(16) __nv_bfloat16 g_WGTh[DD * 32];
__device__ __align__(16) __nv_bfloat16 g_WGTl[DD * 32];

// ---------------- helpers ----------------
__device__ __forceinline__ float tanh_approx(float x) {
    float y;
    asm("tanh.approx.f32 %0, %1;" : "=f"(y) : "f"(x));
    return y;
}
__device__ __forceinline__ float silu_fast(float x) {   // x * sigmoid(x), 1 MUFU
    return x * fmaf(tanh_approx(x * 0.5f), 0.5f, 0.5f);
}

#define MMA16816(d, a, b0v, b1v) \
    asm volatile("mma.sync.aligned.m16n8k16.row.col.f32.bf16.bf16.f32 " \
        "{%0,%1,%2,%3}, {%4,%5,%6,%7}, {%8,%9}, {%0,%1,%2,%3};" \
        : "+f"((d)[0]), "+f"((d)[1]), "+f"((d)[2]), "+f"((d)[3]) \
        : "r"((a)[0]), "r"((a)[1]), "r"((a)[2]), "r"((a)[3]), "r"(b0v), "r"(b1v))

// ---------------------------------------------------------------------------
// Setup: grid=256 (block b = output column n).
//   threads 0..255 (t=k): W^T bf16 hi/lo split.
//   threads 0..31  (t=c): WGT[n][c] = sum_k Wb[c,k]*G[k,n] (c<24), bias row c=24,
//                         zeros c=25..31.  bf16 hi/lo split.
// ---------------------------------------------------------------------------
__global__ void moon_setup(const float* __restrict__ Wb,   // [24,32]
                           const float* __restrict__ bb,   // [32]
                           const float* __restrict__ G,    // [32,256]
                           const float* __restrict__ W)    // [256,256]
{
    const int n = blockIdx.x;
    const int t = threadIdx.x;
    {
        const float w = W[t * DD + n];
        const __nv_bfloat16 h = __float2bfloat16(w);
        g_WTh[n * DD + t] = h;
        g_WTl[n * DD + t] = __float2bfloat16(w - __bfloat162float(h));
    }
    if (t < 32) {
        const int c = t;
        float a = 0.0f;
        if (c < 24) {
            #pragma unroll
            for (int k = 0; k < 32; k++) a += Wb[c * 32 + k] * G[k * DD + n];
        } else if (c == 24) {
            #pragma unroll
            for (int k = 0; k < 32; k++) a += bb[k] * G[k * DD + n];
        }
        const __nv_bfloat16 h = __float2bfloat16(a);
        g_WGTh[n * 32 + c] = h;
        g_WGTl[n * 32 + c] = __float2bfloat16(a - __bfloat162float(h));
    }
}

// ---------------------------------------------------------------------------
// Phase 1: one CTA = 2 rows, 256 threads (8 warps: row = wid>>2, N-slice 64/warp).
// Stage 1: z (bf16 hi/lo, fcut folded, c padded to 32) + inp -> smem.
// Stage 2: gam = z @ WGT via mma.sync (3-chain compensated bf16),
//          res_d = sum_n silu(inp.w1[d]) * gam[n,d] with gam in accumulator frags,
//          butterfly-reduce over the 8 n-groups, store bf16 hi/lo to g_Ah/g_Al.
// ---------------------------------------------------------------------------
__global__ __launch_bounds__(256, 2) void moon_phase1(
    const float* __restrict__ r,
    const float* __restrict__ r_nb,
    const float* __restrict__ ee_scales,
    const float* __restrict__ ee_kernel,
    const float* __restrict__ ee_bias,
    const float* __restrict__ dense1_kernel,
    const float* __restrict__ dense1_bias)
{
    __shared__ __align__(16) __nv_bfloat16 sZh[2][NNB][ZS];
    __shared__ __align__(16) __nv_bfloat16 sZl[2][NNB][ZS];
    __shared__ __align__(16) float s_inp[2][NNB][4];
    __shared__ __align__(16) float s_w[4][DD];
    __shared__ __align__(16) float s_b[DD];

    const int t = threadIdx.x;

    // stage dense1 weights
    #pragma unroll
    for (int i = 0; i < 4; i++) ((float*)s_w)[t + i * 256] = dense1_kernel[t + i * 256];
    s_b[t] = dense1_bias[t];

    const int half = t >> 7;
    const int u    = t & 127;
    const long row = (long)blockIdx.x * 2 + half;

    // ---------------- stage 1 ----------------
    {
        const int n = u >> 2;
        const int j = u & 3;

        const float rx = r[row * 3 + 0];
        const float ry = r[row * 3 + 1];
        const float rz = r[row * 3 + 2];
        const float* nb = r_nb + (row * NNB + n) * 3;
        const float dx = nb[0] - rx;
        const float dy = nb[1] - ry;
        const float dz = nb[2] - rz;
        const float dist = sqrtf(dx * dx + dy * dy + dz * dz);

        const float x = dist * 0.2f;
        const float fcut = (x < 1.0f)
            ? 0.5f * (__cosf(3.14159265358979323846f * x) + 1.0f)
            : 0.0f;

        #pragma unroll
        for (int kk = 0; kk < 4; kk++) {
            const int k = j * 4 + kk;
            float a = ee_bias[k]
                    + dist * ee_kernel[0 * F0 + k]
                    + dx   * ee_kernel[1 * F0 + k]
                    + dy   * ee_kernel[2 * F0 + k]
                    + dz   * ee_kernel[3 * F0 + k];
            const float v = tanh_approx(a) * fcut;
            const __nv_bfloat16 h = __float2bfloat16(v);
            sZh[half][n][k] = h;
            sZl[half][n][k] = __float2bfloat16(v - __bfloat162float(h));
        }
        #pragma unroll
        for (int m = 0; m < 2; m++) {
            const int e = j * 2 + m;
            const float q = __fdividef(dist, ee_scales[e]);
            const float v = __expf(-q * q) * fcut;
            const __nv_bfloat16 h = __float2bfloat16(v);
            sZh[half][n][F0 + e] = h;
            sZl[half][n][F0 + e] = __float2bfloat16(v - __bfloat162float(h));
        }
        if (j == 0) {
            const uint4 z4 = make_uint4(0u, 0u, 0u, 0u);
            *(uint4*)&sZh[half][n][24] = z4;      // zero c=24..31
            *(uint4*)&sZl[half][n][24] = z4;
            const __nv_bfloat16 hc = __float2bfloat16(fcut);
            sZh[half][n][24] = hc;                // constant column (bias row of WG)
            sZl[half][n][24] = __float2bfloat16(fcut - __bfloat162float(hc));

            const float lp = __logf(1.0f + dist);
            const float sc = __fdividef(lp, dist);
            s_inp[half][n][0] = lp;
            s_inp[half][n][1] = dx * sc;
            s_inp[half][n][2] = dy * sc;
            s_inp[half][n][3] = dz * sc;
        }
    }
    __syncthreads();

    // ---------------- stage 2: mma gam + feat product-reduce ----------------
    {
        const int lane = t & 31;
        const int wid  = t >> 5;
        const int gid  = lane >> 2;    // 0..7
        const int tig  = lane & 3;     // 0..3
        const int prow = wid >> 2;     // row within CTA
        const int warpN = (wid & 3) * 64;
        const long grow = (long)blockIdx.x * 2 + prow;

        // A fragments from smem z (M=32 rows n, K=32 cols c)
        uint32_t azh[2][2][4], azl[2][2][4];
        #pragma unroll
        for (int mf = 0; mf < 2; mf++)
            #pragma unroll
            for (int kf = 0; kf < 2; kf++) {
                const int n0 = mf * 16 + gid;
                const int n1 = n0 + 8;
                const int k  = kf * 16 + 2 * tig;
                azh[mf][kf][0] = *(const uint32_t*)&sZh[prow][n0][k];
                azh[mf][kf][1] = *(const uint32_t*)&sZh[prow][n1][k];
                azh[mf][kf][2] = *(const uint32_t*)&sZh[prow][n0][k + 8];
                azh[mf][kf][3] = *(const uint32_t*)&sZh[prow][n1][k + 8];
                azl[mf][kf][0] = *(const uint32_t*)&sZl[prow][n0][k];
                azl[mf][kf][1] = *(const uint32_t*)&sZl[prow][n1][k];
                azl[mf][kf][2] = *(const uint32_t*)&sZl[prow][n0][k + 8];
                azl[mf][kf][3] = *(const uint32_t*)&sZl[prow][n1][k + 8];
            }

        #pragma unroll
        for (int hn = 0; hn < 2; hn++) {          // two 32-wide N slices
            float acc[2][4][4];
            #pragma unroll
            for (int mf = 0; mf < 2; mf++)
                #pragma unroll
                for (int nf = 0; nf < 4; nf++)
                    #pragma unroll
                    for (int c = 0; c < 4; c++) acc[mf][nf][c] = 0.0f;

            #pragma unroll
            for (int nf = 0; nf < 4; nf++) {
                const int ncol = warpN + hn * 32 + nf * 8 + gid;
                const __nv_bfloat16* ph = &g_WGTh[ncol * 32];
                const __nv_bfloat16* pl = &g_WGTl[ncol * 32];
                #pragma unroll
                for (int kf = 0; kf < 2; kf++) {
                    const uint32_t bh0 = *(const uint32_t*)&ph[kf * 16 + 2 * tig];
                    const uint32_t bh1 = *(const uint32_t*)&ph[kf * 16 + 8 + 2 * tig];
                    const uint32_t bl0 = *(const uint32_t*)&pl[kf * 16 + 2 * tig];
                    const uint32_t bl1 = *(const uint32_t*)&pl[kf * 16 + 8 + 2 * tig];
                    #pragma unroll
                    for (int mf = 0; mf < 2; mf++) MMA16816(acc[mf][nf], azh[mf][kf], bh0, bh1);
                    #pragma unroll
                    for (int mf = 0; mf < 2; mf++) MMA16816(acc[mf][nf], azh[mf][kf], bl0, bl1);
                    #pragma unroll
                    for (int mf = 0; mf < 2; mf++) MMA16816(acc[mf][nf], azl[mf][kf], bh0, bh1);
                }
            }

            // feat * gam, reduce over n
            #pragma unroll
            for (int nf = 0; nf < 4; nf++) {
                const int d0 = warpN + hn * 32 + nf * 8 + 2 * tig;
                const float w00 = s_w[0][d0], w01 = s_w[0][d0 + 1];
                const float w10 = s_w[1][d0], w11 = s_w[1][d0 + 1];
                const float w20 = s_w[2][d0], w21 = s_w[2][d0 + 1];
                const float w30 = s_w[3][d0], w31 = s_w[3][d0 + 1];
                const float b0  = s_b[d0],    b1  = s_b[d0 + 1];

                float s0 = 0.0f, s1 = 0.0f;
                #pragma unroll
                for (int mf = 0; mf < 2; mf++)
                    #pragma unroll
                    for (int rh = 0; rh < 2; rh++) {
                        const int n = mf * 16 + rh * 8 + gid;
                        const float4 ip = *(const float4*)s_inp[prow][n];
                        float pre0 = fmaf(ip.x, w00, fmaf(ip.y, w10, fmaf(ip.z, w20, fmaf(ip.w, w30, b0))));
                        float pre1 = fmaf(ip.x, w01, fmaf(ip.y, w11, fmaf(ip.z, w21, fmaf(ip.w, w31, b1))));
                        const float f0 = silu_fast(pre0);
                        const float f1 = silu_fast(pre1);
                        s0 = fmaf(f0, acc[mf][nf][rh * 2 + 0], s0);
                        s1 = fmaf(f1, acc[mf][nf][rh * 2 + 1], s1);
                    }
                // butterfly over gid (lane bits 2..4)
                s0 += __shfl_xor_sync(0xffffffffu, s0, 4);
                s1 += __shfl_xor_sync(0xffffffffu, s1, 4);
                s0 += __shfl_xor_sync(0xffffffffu, s0, 8);
                s1 += __shfl_xor_sync(0xffffffffu, s1, 8);
                s0 += __shfl_xor_sync(0xffffffffu, s0, 16);
                s1 += __shfl_xor_sync(0xffffffffu, s1, 16);

                if (gid == 0) {
                    const __nv_bfloat16 h0 = __float2bfloat16(s0);
                    const __nv_bfloat16 h1 = __float2bfloat16(s1);
                    *(__nv_bfloat162*)&g_Ah[grow * DD + d0] = __halves2bfloat162(h0, h1);
                    const __nv_bfloat16 l0 = __float2bfloat16(s0 - __bfloat162float(h0));
                    const __nv_bfloat16 l1 = __float2bfloat16(s1 - __bfloat162float(h1));
                    *(__nv_bfloat162*)&g_Al[grow * DD + d0] = __halves2bfloat162(l0, l1);
                }
            }
        }
    }
}

// ---------------------------------------------------------------------------
// Kernel B (unchanged, proven): Y = silu(A @ W + bias), 3-chain compensated bf16.
// ---------------------------------------------------------------------------
constexpr int KS = 88;
constexpr int TILE_BYTES = 128 * KS * 2;

__global__ __launch_bounds__(256) void moon_gemm_mma(
    const float* __restrict__ bias, float* __restrict__ Y)
{
    extern __shared__ __align__(16) char smem[];
    __nv_bfloat16* sAh = (__nv_bfloat16*)(smem);
    __nv_bfloat16* sAl = (__nv_bfloat16*)(smem + TILE_BYTES);
    __nv_bfloat16* sBh = (__nv_bfloat16*)(smem + 2 * TILE_BYTES);
    __nv_bfloat16* sBl = (__nv_bfloat16*)(smem + 3 * TILE_BYTES);

    const int t    = threadIdx.x;
    const int lane = t & 31;
    const int wid  = t >> 5;
    const int gid  = lane >> 2;
    const int tig  = lane & 3;
    const int warp_m = wid & 3;
    const int warp_n = wid >> 2;
    const int ct   = blockIdx.x;
    const int rowT = blockIdx.y;

    float acc[2][8][4];
    #pragma unroll
    for (int mf = 0; mf < 2; mf++)
        #pragma unroll
        for (int j = 0; j < 8; j++)
            #pragma unroll
            for (int c = 0; c < 4; c++) acc[mf][j][c] = 0.0f;

    const size_t aBase = (size_t)(rowT * 128) * DD;
    const size_t bBase = (size_t)(ct * 128) * DD;

    for (int kc = 0; kc < 4; kc++) {
        #pragma unroll
        for (int i = 0; i < 4; i++) {
            const int lin = t + i * 256;
            const int rr  = lin >> 3;
            const int kq  = (lin & 7) * 8;
            const size_t goff = (size_t)rr * DD + kc * 64 + kq;
            const int soff = rr * KS + kq;
            *(uint4*)&sAh[soff] = *(const uint4*)&g_Ah[aBase + goff];
            *(uint4*)&sAl[soff] = *(const uint4*)&g_Al[aBase + goff];
            *(uint4*)&sBh[soff] = *(const uint4*)&g_WTh[bBase + goff];
            *(uint4*)&sBl[soff] = *(const uint4*)&g_WTl[bBase + goff];
        }
        __syncthreads();

        #pragma unroll
        for (int k16 = 0; k16 < 4; k16++) {
            const int koff = k16 * 16;
            uint32_t ah[2][4], al[2][4];
            #pragma unroll
            for (int mf = 0; mf < 2; mf++) {
                const int mb = warp_m * 32 + mf * 16;
                const int r0 = (mb + gid) * KS + koff + 2 * tig;
                const int r1 = (mb + 8 + gid) * KS + koff + 2 * tig;
                ah[mf][0] = *(const uint32_t*)&sAh[r0];
                ah[mf][1] = *(const uint32_t*)&sAh[r1];
                ah[mf][2] = *(const uint32_t*)&sAh[r0 + 8];
                ah[mf][3] = *(const uint32_t*)&sAh[r1 + 8];
                al[mf][0] = *(const uint32_t*)&sAl[r0];
                al[mf][1] = *(const uint32_t*)&sAl[r1];
                al[mf][2] = *(const uint32_t*)&sAl[r0 + 8];
                al[mf][3] = *(const uint32_t*)&sAl[r1 + 8];
            }
            #pragma unroll
            for (int j = 0; j < 8; j++) {
                const int nb = (warp_n * 64 + j * 8 + gid) * KS + koff + 2 * tig;
                const uint32_t bh0 = *(const uint32_t*)&sBh[nb];
                const uint32_t bh1 = *(const uint32_t*)&sBh[nb + 8];
                const uint32_t bl0 = *(const uint32_t*)&sBl[nb];
                const uint32_t bl1 = *(const uint32_t*)&sBl[nb + 8];
                #pragma unroll
                for (int mf = 0; mf < 2; mf++) {
                    MMA16816(acc[mf][j], ah[mf], bh0, bh1);
                    MMA16816(acc[mf][j], ah[mf], bl0, bl1);
                    MMA16816(acc[mf][j], al[mf], bh0, bh1);
                }
            }
        }
        __syncthreads();
    }

    #pragma unroll
    for (int j = 0; j < 8; j++) {
        const int col = ct * 128 + warp_n * 64 + j * 8 + 2 * tig;
        const float2 bb = *(const float2*)&bias[col];
        #pragma unroll
        for (int mf = 0; mf < 2; mf++) {
            const long row0 = rowT * 128 + warp_m * 32 + mf * 16 + gid;
            float v0 = acc[mf][j][0] + bb.x;
            float v1 = acc[mf][j][1] + bb.y;
            float v2 = acc[mf][j][2] + bb.x;
            float v3 = acc[mf][j][3] + bb.y;
            float2 o0, o1;
            o0.x = __fdividef(v0, 1.0f + __expf(-v0));
            o0.y = __fdividef(v1, 1.0f + __expf(-v1));
            o1.x = __fdividef(v2, 1.0f + __expf(-v2));
            o1.y = __fdividef(v3, 1.0f + __expf(-v3));
            *(float2*)&Y[row0 * DD + col]       = o0;
            *(float2*)&Y[(row0 + 8) * DD + col] = o1;
        }
    }
}

// ---------------------------------------------------------------------------
extern "C" void kernel_launch(void* const* d_in, const int* in_sizes, int n_in,
                              void* d_out, int out_size)
{
    const float* r             = (const float*)d_in[0];
    const float* r_nb          = (const float*)d_in[1];
    const float* ee_scales     = (const float*)d_in[2];
    const float* ee_kernel     = (const float*)d_in[3];
    const float* ee_bias       = (const float*)d_in[4];
    const float* beta_kernel   = (const float*)d_in[5];
    const float* beta_bias     = (const float*)d_in[6];
    const float* gamma_kernel  = (const float*)d_in[7];
    const float* dense1_kernel = (const float*)d_in[8];
    const float* dense1_bias   = (const float*)d_in[9];
    const float* out_kernel    = (const float*)d_in[10];
    const float* out_bias      = (const float*)d_in[11];

    const int rows = in_sizes[0] / 3;  // 8192

    static bool attr_done = false;
    if (!attr_done) {
        cudaFuncSetAttribute(moon_gemm_mma,
                             cudaFuncAttributeMaxDynamicSharedMemorySize,
                             4 * TILE_BYTES);
        attr_done = true;
    }

    moon_setup<<<256, 256>>>(beta_kernel, beta_bias, gamma_kernel, out_kernel);

    moon_phase1<<<rows / 2, 256>>>(r, r_nb, ee_scales, ee_kernel, ee_bias,
                                   dense1_kernel, dense1_bias);

    dim3 gridB(2, rows / 128);
    moon_gemm_mma<<<gridB, 256, 4 * TILE_BYTES>>>(out_bias, (float*)d_out);
}

// round 10
// speedup vs baseline: 4.7521x; 1.1351x over previous
#include <cuda_runtime.h>
#include <cuda_bf16.h>
#include <math.h>
#include <stdint.h>

constexpr int NNB  = 32;
constexpr int F0   = 16;
constexpr int DD   = 256;
constexpr int NROWS = 8192;       // B*E
constexpr int ZS   = 40;          // smem z row stride in bf16 (80B, conflict-free frags)
constexpr int WGS  = 36;          // smem WGT row stride in bf16 (72B)

// A (phase1 result) bf16 hi/lo, row-major [8192][256]
__device__ __align__(16) __nv_bfloat16 g_Ah[NROWS * DD];
__device__ __align__(16) __nv_bfloat16 g_Al[NROWS * DD];
// out_kernel^T bf16 hi/lo, row-major [n=256][k=256]
__device__ __align__(16) __nv_bfloat16 g_WTh[DD * DD];
__device__ __align__(16) __nv_bfloat16 g_WTl[DD * DD];
// WG^T = (fold of beta_kernel/bias @ gamma)^T, bf16 hi/lo, [d=256][c=32] (c>=25 zero)
__device__ __align__(16) __nv_bfloat16 g_WGTh[DD * 32];
__device__ __align__(16) __nv_bfloat16 g_WGTl[DD * 32];

// ---------------- helpers ----------------
typedef unsigned long long ull;
__device__ __forceinline__ ull pack2(float lo, float hi) {
    ull r;
    asm("mov.b64 %0, {%1, %2};" : "=l"(r) : "f"(lo), "f"(hi));
    return r;
}
__device__ __forceinline__ ull fma2(ull a, ull b, ull c) {
    ull d;
    asm("fma.rn.f32x2 %0, %1, %2, %3;" : "=l"(d) : "l"(a), "l"(b), "l"(c));
    return d;
}
__device__ __forceinline__ ull mul2(ull a, ull b) {
    ull d;
    asm("mul.rn.f32x2 %0, %1, %2;" : "=l"(d) : "l"(a), "l"(b));
    return d;
}
__device__ __forceinline__ float2 unpack2(ull v) {
    float2 r;
    asm("mov.b64 {%0, %1}, %2;" : "=f"(r.x), "=f"(r.y) : "l"(v));
    return r;
}
__device__ __forceinline__ float tanh_approx(float x) {
    float y;
    asm("tanh.approx.f32 %0, %1;" : "=f"(y) : "f"(x));
    return y;
}

#define MMA16816(d, a, b0v, b1v) \
    asm volatile("mma.sync.aligned.m16n8k16.row.col.f32.bf16.bf16.f32 " \
        "{%0,%1,%2,%3}, {%4,%5,%6,%7}, {%8,%9}, {%0,%1,%2,%3};" \
        : "+f"((d)[0]), "+f"((d)[1]), "+f"((d)[2]), "+f"((d)[3]) \
        : "r"((a)[0]), "r"((a)[1]), "r"((a)[2]), "r"((a)[3]), "r"(b0v), "r"(b1v))

// ---------------------------------------------------------------------------
// Setup: grid=256 (block = output column n).
//   all 256 threads (t=k): W^T bf16 hi/lo split.
//   all 256 threads: WG dot split 8 ways (c = t>>3, kg = t&7) + shfl reduce.
// ---------------------------------------------------------------------------
__global__ void moon_setup(const float* __restrict__ Wb,   // [24,32]
                           const float* __restrict__ bb,   // [32]
                           const float* __restrict__ G,    // [32,256]
                           const float* __restrict__ W)    // [256,256]
{
    const int n = blockIdx.x;
    const int t = threadIdx.x;
    {
        const float w = W[t * DD + n];
        const __nv_bfloat16 h = __float2bfloat16(w);
        g_WTh[n * DD + t] = h;
        g_WTl[n * DD + t] = __float2bfloat16(w - __bfloat162float(h));
    }
    {
        const int c  = t >> 3;    // 0..31
        const int kg = t & 7;     // 0..7
        float a = 0.0f;
        if (c < 24) {
            #pragma unroll
            for (int q = 0; q < 4; q++) {
                const int k = kg * 4 + q;
                a += Wb[c * 32 + k] * G[k * DD + n];
            }
        } else if (c == 24) {
            #pragma unroll
            for (int q = 0; q < 4; q++) {
                const int k = kg * 4 + q;
                a += bb[k] * G[k * DD + n];
            }
        }
        a += __shfl_xor_sync(0xffffffffu, a, 1);
        a += __shfl_xor_sync(0xffffffffu, a, 2);
        a += __shfl_xor_sync(0xffffffffu, a, 4);
        if (kg == 0) {
            const __nv_bfloat16 h = __float2bfloat16(a);
            g_WGTh[n * 32 + c] = h;
            g_WGTl[n * 32 + c] = __float2bfloat16(a - __bfloat162float(h));
        }
    }
}

// ---------------------------------------------------------------------------
// Phase 1: one CTA = 2 rows, 256 threads.
// z single bf16 (2-chain MMA vs hi/lo WGT staged in smem);
// product-reduce packed in f32x2 over adjacent-d pairs.
// ---------------------------------------------------------------------------
__global__ __launch_bounds__(256, 2) void moon_phase1(
    const float* __restrict__ r,
    const float* __restrict__ r_nb,
    const float* __restrict__ ee_scales,
    const float* __restrict__ ee_kernel,
    const float* __restrict__ ee_bias,
    const float* __restrict__ dense1_kernel,
    const float* __restrict__ dense1_bias)
{
    __shared__ __align__(16) __nv_bfloat16 sZh[2][NNB][ZS];       // 5 KB
    __shared__ __align__(16) float s_inp[2][NNB][4];              // 1 KB
    __shared__ __align__(16) float s_w[4][DD];                    // 4 KB
    __shared__ __align__(16) float s_b[DD];                       // 1 KB
    __shared__ __align__(16) __nv_bfloat16 sWGh[DD * WGS];        // 18 KB
    __shared__ __align__(16) __nv_bfloat16 sWGl[DD * WGS];        // 18 KB

    const int t = threadIdx.x;

    // stage dense1 weights + bias
    #pragma unroll
    for (int i = 0; i < 4; i++) ((float*)s_w)[t + i * 256] = dense1_kernel[t + i * 256];
    s_b[t] = dense1_bias[t];

    // stage WGT hi/lo into padded smem (n = t, 32 c each; 8B stores since 72B rows)
    {
        const uint2* srcH = (const uint2*)&g_WGTh[t * 32];
        const uint2* srcL = (const uint2*)&g_WGTl[t * 32];
        uint2* dstH = (uint2*)&sWGh[t * WGS];
        uint2* dstL = (uint2*)&sWGl[t * WGS];
        #pragma unroll
        for (int i = 0; i < 8; i++) { dstH[i] = srcH[i]; dstL[i] = srcL[i]; }
    }

    const int half = t >> 7;
    const int u    = t & 127;
    const long row = (long)blockIdx.x * 2 + half;

    // ---------------- stage 1 ----------------
    {
        const int n = u >> 2;
        const int j = u & 3;

        const float rx = r[row * 3 + 0];
        const float ry = r[row * 3 + 1];
        const float rz = r[row * 3 + 2];
        const float* nb = r_nb + (row * NNB + n) * 3;
        const float dx = nb[0] - rx;
        const float dy = nb[1] - ry;
        const float dz = nb[2] - rz;
        const float dist = sqrtf(dx * dx + dy * dy + dz * dz);

        const float x = dist * 0.2f;
        const float fcut = (x < 1.0f)
            ? 0.5f * (__cosf(3.14159265358979323846f * x) + 1.0f)
            : 0.0f;

        #pragma unroll
        for (int kk = 0; kk < 4; kk++) {
            const int k = j * 4 + kk;
            float a = ee_bias[k]
                    + dist * ee_kernel[0 * F0 + k]
                    + dx   * ee_kernel[1 * F0 + k]
                    + dy   * ee_kernel[2 * F0 + k]
                    + dz   * ee_kernel[3 * F0 + k];
            sZh[half][n][k] = __float2bfloat16(tanh_approx(a) * fcut);
        }
        #pragma unroll
        for (int m = 0; m < 2; m++) {
            const int e = j * 2 + m;
            const float q = __fdividef(dist, ee_scales[e]);
            sZh[half][n][F0 + e] = __float2bfloat16(__expf(-q * q) * fcut);
        }
        if (j == 0) {
            *(uint4*)&sZh[half][n][24] = make_uint4(0u, 0u, 0u, 0u);
            sZh[half][n][24] = __float2bfloat16(fcut);   // bias column of WG

            const float lp = __logf(1.0f + dist);
            const float sc = __fdividef(lp, dist);
            s_inp[half][n][0] = lp;
            s_inp[half][n][1] = dx * sc;
            s_inp[half][n][2] = dy * sc;
            s_inp[half][n][3] = dz * sc;
        }
    }
    __syncthreads();

    // ---------------- stage 2 ----------------
    {
        const int lane = t & 31;
        const int wid  = t >> 5;
        const int gid  = lane >> 2;    // 0..7
        const int tig  = lane & 3;     // 0..3
        const int prow = wid >> 2;     // row within CTA
        const int warpN = (wid & 3) * 64;
        const long grow = (long)blockIdx.x * 2 + prow;

        // A fragments (z, single bf16)
        uint32_t azh[2][2][4];
        #pragma unroll
        for (int mf = 0; mf < 2; mf++)
            #pragma unroll
            for (int kf = 0; kf < 2; kf++) {
                const int n0 = mf * 16 + gid;
                const int n1 = n0 + 8;
                const int k  = kf * 16 + 2 * tig;
                azh[mf][kf][0] = *(const uint32_t*)&sZh[prow][n0][k];
                azh[mf][kf][1] = *(const uint32_t*)&sZh[prow][n1][k];
                azh[mf][kf][2] = *(const uint32_t*)&sZh[prow][n0][k + 8];
                azh[mf][kf][3] = *(const uint32_t*)&sZh[prow][n1][k + 8];
            }

        // hoisted ip packs: n = {gid, 8+gid, 16+gid, 24+gid}  (it = mf*2+rh)
        ull ipp[4][4];
        #pragma unroll
        for (int it = 0; it < 4; it++) {
            const int n = ((it >> 1) * 16) + ((it & 1) * 8) + gid;
            const float4 ip = *(const float4*)s_inp[prow][n];
            ipp[it][0] = pack2(ip.x, ip.x);
            ipp[it][1] = pack2(ip.y, ip.y);
            ipp[it][2] = pack2(ip.z, ip.z);
            ipp[it][3] = pack2(ip.w, ip.w);
        }
        const ull K05 = pack2(0.5f, 0.5f);

        #pragma unroll
        for (int hn = 0; hn < 2; hn++) {
            float acc[2][4][4];
            #pragma unroll
            for (int mf = 0; mf < 2; mf++)
                #pragma unroll
                for (int nf = 0; nf < 4; nf++)
                    #pragma unroll
                    for (int c = 0; c < 4; c++) acc[mf][nf][c] = 0.0f;

            #pragma unroll
            for (int nf = 0; nf < 4; nf++) {
                const int ncol = warpN + hn * 32 + nf * 8 + gid;
                const __nv_bfloat16* ph = &sWGh[ncol * WGS];
                const __nv_bfloat16* pl = &sWGl[ncol * WGS];
                #pragma unroll
                for (int kf = 0; kf < 2; kf++) {
                    const uint32_t bh0 = *(const uint32_t*)&ph[kf * 16 + 2 * tig];
                    const uint32_t bh1 = *(const uint32_t*)&ph[kf * 16 + 8 + 2 * tig];
                    const uint32_t bl0 = *(const uint32_t*)&pl[kf * 16 + 2 * tig];
                    const uint32_t bl1 = *(const uint32_t*)&pl[kf * 16 + 8 + 2 * tig];
                    MMA16816(acc[0][nf], azh[0][kf], bh0, bh1);
                    MMA16816(acc[1][nf], azh[1][kf], bh0, bh1);
                    MMA16816(acc[0][nf], azh[0][kf], bl0, bl1);
                    MMA16816(acc[1][nf], azh[1][kf], bl0, bl1);
                }
            }

            // packed product-reduce
            #pragma unroll
            for (int nf = 0; nf < 4; nf++) {
                const int d0 = warpN + hn * 32 + nf * 8 + 2 * tig;
                const ull wp0 = *(const ull*)&s_w[0][d0];
                const ull wp1 = *(const ull*)&s_w[1][d0];
                const ull wp2 = *(const ull*)&s_w[2][d0];
                const ull wp3 = *(const ull*)&s_w[3][d0];
                const ull bp  = *(const ull*)&s_b[d0];

                ull s2 = 0ull;
                #pragma unroll
                for (int it = 0; it < 4; it++) {
                    ull pre2 = fma2(ipp[it][0], wp0,
                               fma2(ipp[it][1], wp1,
                               fma2(ipp[it][2], wp2,
                               fma2(ipp[it][3], wp3, bp))));
                    const ull ph2 = mul2(pre2, K05);
                    const float2 pu = unpack2(ph2);
                    const ull tp = pack2(tanh_approx(pu.x), tanh_approx(pu.y));
                    const ull sg = fma2(tp, K05, K05);
                    const ull feat2 = mul2(pre2, sg);
                    const ull gam2 = pack2(acc[it >> 1][nf][(it & 1) * 2],
                                           acc[it >> 1][nf][(it & 1) * 2 + 1]);
                    s2 = fma2(feat2, gam2, s2);
                }

                float2 sv = unpack2(s2);
                sv.x += __shfl_xor_sync(0xffffffffu, sv.x, 4);
                sv.y += __shfl_xor_sync(0xffffffffu, sv.y, 4);
                sv.x += __shfl_xor_sync(0xffffffffu, sv.x, 8);
                sv.y += __shfl_xor_sync(0xffffffffu, sv.y, 8);
                sv.x += __shfl_xor_sync(0xffffffffu, sv.x, 16);
                sv.y += __shfl_xor_sync(0xffffffffu, sv.y, 16);

                if (gid == 0) {
                    const __nv_bfloat16 h0 = __float2bfloat16(sv.x);
                    const __nv_bfloat16 h1 = __float2bfloat16(sv.y);
                    *(__nv_bfloat162*)&g_Ah[grow * DD + d0] = __halves2bfloat162(h0, h1);
                    const __nv_bfloat16 l0 = __float2bfloat16(sv.x - __bfloat162float(h0));
                    const __nv_bfloat16 l1 = __float2bfloat16(sv.y - __bfloat162float(h1));
                    *(__nv_bfloat162*)&g_Al[grow * DD + d0] = __halves2bfloat162(l0, l1);
                }
            }
        }
    }
}

// ---------------------------------------------------------------------------
// Kernel B (unchanged, proven): Y = silu(A @ W + bias), 3-chain compensated bf16.
// ---------------------------------------------------------------------------
constexpr int KS = 88;
constexpr int TILE_BYTES = 128 * KS * 2;

__global__ __launch_bounds__(256) void moon_gemm_mma(
    const float* __restrict__ bias, float* __restrict__ Y)
{
    extern __shared__ __align__(16) char smem[];
    __nv_bfloat16* sAh = (__nv_bfloat16*)(smem);
    __nv_bfloat16* sAl = (__nv_bfloat16*)(smem + TILE_BYTES);
    __nv_bfloat16* sBh = (__nv_bfloat16*)(smem + 2 * TILE_BYTES);
    __nv_bfloat16* sBl = (__nv_bfloat16*)(smem + 3 * TILE_BYTES);

    const int t    = threadIdx.x;
    const int lane = t & 31;
    const int wid  = t >> 5;
    const int gid  = lane >> 2;
    const int tig  = lane & 3;
    const int warp_m = wid & 3;
    const int warp_n = wid >> 2;
    const int ct   = blockIdx.x;
    const int rowT = blockIdx.y;

    float acc[2][8][4];
    #pragma unroll
    for (int mf = 0; mf < 2; mf++)
        #pragma unroll
        for (int j = 0; j < 8; j++)
            #pragma unroll
            for (int c = 0; c < 4; c++) acc[mf][j][c] = 0.0f;

    const size_t aBase = (size_t)(rowT * 128) * DD;
    const size_t bBase = (size_t)(ct * 128) * DD;

    for (int kc = 0; kc < 4; kc++) {
        #pragma unroll
        for (int i = 0; i < 4; i++) {
            const int lin = t + i * 256;
            const int rr  = lin >> 3;
            const int kq  = (lin & 7) * 8;
            const size_t goff = (size_t)rr * DD + kc * 64 + kq;
            const int soff = rr * KS + kq;
            *(uint4*)&sAh[soff] = *(const uint4*)&g_Ah[aBase + goff];
            *(uint4*)&sAl[soff] = *(const uint4*)&g_Al[aBase + goff];
            *(uint4*)&sBh[soff] = *(const uint4*)&g_WTh[bBase + goff];
            *(uint4*)&sBl[soff] = *(const uint4*)&g_WTl[bBase + goff];
        }
        __syncthreads();

        #pragma unroll
        for (int k16 = 0; k16 < 4; k16++) {
            const int koff = k16 * 16;
            uint32_t ah[2][4], al[2][4];
            #pragma unroll
            for (int mf = 0; mf < 2; mf++) {
                const int mb = warp_m * 32 + mf * 16;
                const int r0 = (mb + gid) * KS + koff + 2 * tig;
                const int r1 = (mb + 8 + gid) * KS + koff + 2 * tig;
                ah[mf][0] = *(const uint32_t*)&sAh[r0];
                ah[mf][1] = *(const uint32_t*)&sAh[r1];
                ah[mf][2] = *(const uint32_t*)&sAh[r0 + 8];
                ah[mf][3] = *(const uint32_t*)&sAh[r1 + 8];
                al[mf][0] = *(const uint32_t*)&sAl[r0];
                al[mf][1] = *(const uint32_t*)&sAl[r1];
                al[mf][2] = *(const uint32_t*)&sAl[r0 + 8];
                al[mf][3] = *(const uint32_t*)&sAl[r1 + 8];
            }
            #pragma unroll
            for (int j = 0; j < 8; j++) {
                const int nb = (warp_n * 64 + j * 8 + gid) * KS + koff + 2 * tig;
                const uint32_t bh0 = *(const uint32_t*)&sBh[nb];
                const uint32_t bh1 = *(const uint32_t*)&sBh[nb + 8];
                const uint32_t bl0 = *(const uint32_t*)&sBl[nb];
                const uint32_t bl1 = *(const uint32_t*)&sBl[nb + 8];
                #pragma unroll
                for (int mf = 0; mf < 2; mf++) {
                    MMA16816(acc[mf][j], ah[mf], bh0, bh1);
                    MMA16816(acc[mf][j], ah[mf], bl0, bl1);
                    MMA16816(acc[mf][j], al[mf], bh0, bh1);
                }
            }
        }
        __syncthreads();
    }

    #pragma unroll
    for (int j = 0; j < 8; j++) {
        const int col = ct * 128 + warp_n * 64 + j * 8 + 2 * tig;
        const float2 bb = *(const float2*)&bias[col];
        #pragma unroll
        for (int mf = 0; mf < 2; mf++) {
            const long row0 = rowT * 128 + warp_m * 32 + mf * 16 + gid;
            float v0 = acc[mf][j][0] + bb.x;
            float v1 = acc[mf][j][1] + bb.y;
            float v2 = acc[mf][j][2] + bb.x;
            float v3 = acc[mf][j][3] + bb.y;
            float2 o0, o1;
            o0.x = __fdividef(v0, 1.0f + __expf(-v0));
            o0.y = __fdividef(v1, 1.0f + __expf(-v1));
            o1.x = __fdividef(v2, 1.0f + __expf(-v2));
            o1.y = __fdividef(v3, 1.0f + __expf(-v3));
            *(float2*)&Y[row0 * DD + col]       = o0;
            *(float2*)&Y[(row0 + 8) * DD + col] = o1;
        }
    }
}

// ---------------------------------------------------------------------------
extern "C" void kernel_launch(void* const* d_in, const int* in_sizes, int n_in,
                              void* d_out, int out_size)
{
    const float* r             = (const float*)d_in[0];
    const float* r_nb          = (const float*)d_in[1];
    const float* ee_scales     = (const float*)d_in[2];
    const float* ee_kernel     = (const float*)d_in[3];
    const float* ee_bias       = (const float*)d_in[4];
    const float* beta_kernel   = (const float*)d_in[5];
    const float* beta_bias     = (const float*)d_in[6];
    const float* gamma_kernel  = (const float*)d_in[7];
    const float* dense1_kernel = (const float*)d_in[8];
    const float* dense1_bias   = (const float*)d_in[9];
    const float* out_kernel    = (const float*)d_in[10];
    const float* out_bias      = (const float*)d_in[11];

    const int rows = in_sizes[0] / 3;  // 8192

    static bool attr_done = false;
    if (!attr_done) {
        cudaFuncSetAttribute(moon_gemm_mma,
                             cudaFuncAttributeMaxDynamicSharedMemorySize,
                             4 * TILE_BYTES);
        attr_done = true;
    }

    moon_setup<<<256, 256>>>(beta_kernel, beta_bias, gamma_kernel, out_kernel);

    moon_phase1<<<rows / 2, 256>>>(r, r_nb, ee_scales, ee_kernel, ee_bias,
                                   dense1_kernel, dense1_bias);

    dim3 gridB(2, rows / 128);
    moon_gemm_mma<<<gridB, 256, 4 * TILE_BYTES>>>(out_bias, (float*)d_out);
}